// round 11
// baseline (speedup 1.0000x reference)
#include <cuda_runtime.h>
#include <cuda_bf16.h>
#include <cstdint>

// out[b,m,c] = sum_{k<3} vals[m,k] * x[b, cols[m,k], c]
//   x: [8, 50000, 128] f32   cols: [25000, 3] i32   vals: [25000, 3] f32
//   out: [8, 25000, 128] f32
//
// DRAM-bound at ~5.8TB/s (MLP=6/12/24-class, cp.async pipeline, L2-policy,
// occupancy variants all equal). Last mechanism: PALINDROMIC WORK ORDER so
// the rows touched at the END of replay i are re-touched at the START of
// replay i+1 (CUDA-graph replays run the same schedule every time):
//   order = [bp0 first-half-m, bp1, bp2, bp3, bp0 second-half-m]
// L2 at replay end holds bp0/secondhalf rows (~27MB); the next replay's
// opening bp0/firsthalf reads hit ~53% of them -> ~12-15MB fewer DRAM reads.
// Base design (best measured, R9): one warp = 2m x 2b, 12 coalesced
// LDG.128, st.global.wt output (no dirty-line L2 cycling).

#define B_DIM 8
#define N_DIM 50000
#define M_DIM 25000
#define C_VEC 32              // 128 floats / 4 per float4
#define BP    (B_DIM / 2)     // 4 batch pairs
#define MI    (M_DIM / 2)     // 12500 m pairs
#define HALF0 (MI / 2)        // 6250: bp0 first-half warps

__device__ __forceinline__ void stwt(float4* p, float4 v) {
    asm volatile("st.global.wt.v4.f32 [%0], {%1,%2,%3,%4};"
                 :: "l"(p), "f"(v.x), "f"(v.y), "f"(v.z), "f"(v.w));
}

__global__ __launch_bounds__(256, 3)
void mesh_sampling_kernel(const float4* __restrict__ x,
                          const int*    __restrict__ cols,
                          const float*  __restrict__ vals,
                          float4*       __restrict__ out)
{
    const int gwarp = (blockIdx.x * blockDim.x + threadIdx.x) >> 5;
    const int lane  = threadIdx.x & 31;
    if (gwarp >= BP * MI) return;

    // Palindromic schedule: [bp0 mi<6250 | bp1 | bp2 | bp3 | bp0 mi>=6250]
    int bp, mi;
    if (gwarp < HALF0) {
        bp = 0; mi = gwarp;
    } else if (gwarp < HALF0 + 3 * MI) {
        const int t = gwarp - HALF0;
        bp = 1 + t / MI;
        mi = t - (bp - 1) * MI;
    } else {
        bp = 0; mi = HALF0 + (gwarp - (HALF0 + 3 * MI));
    }

    const int m0 = mi * 2;
    const int m1 = m0 + 1;
    const int b0 = bp * 2;
    const int b1 = b0 + 1;

    // warp-uniform indices / weights (broadcast, L2-resident)
    const int  c00 = __ldg(cols + m0 * 3 + 0);
    const int  c01 = __ldg(cols + m0 * 3 + 1);
    const int  c02 = __ldg(cols + m0 * 3 + 2);
    const int  c10 = __ldg(cols + m1 * 3 + 0);
    const int  c11 = __ldg(cols + m1 * 3 + 1);
    const int  c12 = __ldg(cols + m1 * 3 + 2);
    const float v00 = __ldg(vals + m0 * 3 + 0);
    const float v01 = __ldg(vals + m0 * 3 + 1);
    const float v02 = __ldg(vals + m0 * 3 + 2);
    const float v10 = __ldg(vals + m1 * 3 + 0);
    const float v11 = __ldg(vals + m1 * 3 + 1);
    const float v12 = __ldg(vals + m1 * 3 + 2);

    const float4* xb0 = x + (size_t)b0 * N_DIM * C_VEC + lane;
    const float4* xb1 = x + (size_t)b1 * N_DIM * C_VEC + lane;

    // 12 independent 16B loads in flight, all 512B-row coalesced
    const float4 a00 = __ldg(xb0 + (size_t)c00 * C_VEC);
    const float4 a01 = __ldg(xb0 + (size_t)c01 * C_VEC);
    const float4 a02 = __ldg(xb0 + (size_t)c02 * C_VEC);
    const float4 a10 = __ldg(xb0 + (size_t)c10 * C_VEC);
    const float4 a11 = __ldg(xb0 + (size_t)c11 * C_VEC);
    const float4 a12 = __ldg(xb0 + (size_t)c12 * C_VEC);
    const float4 a20 = __ldg(xb1 + (size_t)c00 * C_VEC);
    const float4 a21 = __ldg(xb1 + (size_t)c01 * C_VEC);
    const float4 a22 = __ldg(xb1 + (size_t)c02 * C_VEC);
    const float4 a30 = __ldg(xb1 + (size_t)c10 * C_VEC);
    const float4 a31 = __ldg(xb1 + (size_t)c11 * C_VEC);
    const float4 a32 = __ldg(xb1 + (size_t)c12 * C_VEC);

    float4 r;
    // (b0, m0)
    r.x = v00 * a00.x + v01 * a01.x + v02 * a02.x;
    r.y = v00 * a00.y + v01 * a01.y + v02 * a02.y;
    r.z = v00 * a00.z + v01 * a01.z + v02 * a02.z;
    r.w = v00 * a00.w + v01 * a01.w + v02 * a02.w;
    stwt(out + ((size_t)b0 * M_DIM + m0) * C_VEC + lane, r);
    // (b0, m1)
    r.x = v10 * a10.x + v11 * a11.x + v12 * a12.x;
    r.y = v10 * a10.y + v11 * a11.y + v12 * a12.y;
    r.z = v10 * a10.z + v11 * a11.z + v12 * a12.z;
    r.w = v10 * a10.w + v11 * a11.w + v12 * a12.w;
    stwt(out + ((size_t)b0 * M_DIM + m1) * C_VEC + lane, r);
    // (b1, m0)
    r.x = v00 * a20.x + v01 * a21.x + v02 * a22.x;
    r.y = v00 * a20.y + v01 * a21.y + v02 * a22.y;
    r.z = v00 * a20.z + v01 * a21.z + v02 * a22.z;
    r.w = v00 * a20.w + v01 * a21.w + v02 * a22.w;
    stwt(out + ((size_t)b1 * M_DIM + m0) * C_VEC + lane, r);
    // (b1, m1)
    r.x = v10 * a30.x + v11 * a31.x + v12 * a32.x;
    r.y = v10 * a30.y + v11 * a31.y + v12 * a32.y;
    r.z = v10 * a30.z + v11 * a31.z + v12 * a32.z;
    r.w = v10 * a30.w + v11 * a31.w + v12 * a32.w;
    stwt(out + ((size_t)b1 * M_DIM + m1) * C_VEC + lane, r);
}

extern "C" void kernel_launch(void* const* d_in, const int* in_sizes, int n_in,
                              void* d_out, int out_size)
{
    const float4* x    = (const float4*)d_in[0];
    const int*    cols = (const int*)d_in[1];
    const float*  vals = (const float*)d_in[2];
    float4*       out  = (float4*)d_out;

    const int total_warps   = BP * MI;                // 50000
    const int threads       = 256;
    const int warps_per_blk = threads / 32;
    const int blocks        = (total_warps + warps_per_blk - 1) / warps_per_blk;

    mesh_sampling_kernel<<<blocks, threads>>>(x, cols, vals, out);
}

// round 12
// speedup vs baseline: 1.0165x; 1.0165x over previous
#include <cuda_runtime.h>
#include <cuda_bf16.h>
#include <cstdint>

// out[b,m,c] = sum_{k<3} vals[m,k] * x[b, cols[m,k], c]
//   x: [8, 50000, 128] f32   cols: [25000, 3] i32   vals: [25000, 3] f32
//   out: [8, 25000, 128] f32
//
// CONVERGED DESIGN (best of 10 measured mechanisms):
//  - DRAM-bound at ~5.8TB/s for this random-512B-gather + linear-write mix.
//    MLP 3/6/12, cp.async deep pipeline, L2 evict policies, occupancy, and
//    work-order remaps all measured flat; traffic is within ~12% of the
//    compulsory floor (writes compulsory, reads below single-pass floor via
//    natural L2 retention of duplicate rows).
//  - one warp = 2 m-values x 2 batches: 12 independent coalesced LDG.128
//    per lane (every gather row = 4x128B lines, fully coalesced)
//  - st.global.wt output: write-through, so the 102MB write-once stream
//    doesn't cycle dirty lines through L2 (only knob that measurably won)
//  - monotone batch-pair order keeps exactly 2 batch slices hot in L2,
//    maximizing within-replay duplicate-row hits (palindromic remap lost).

#define B_DIM 8
#define N_DIM 50000
#define M_DIM 25000
#define C_VEC 32              // 128 floats / 4 per float4
#define BP    (B_DIM / 2)     // 4 batch pairs
#define MI    (M_DIM / 2)     // 12500 m pairs

__device__ __forceinline__ void stwt(float4* p, float4 v) {
    asm volatile("st.global.wt.v4.f32 [%0], {%1,%2,%3,%4};"
                 :: "l"(p), "f"(v.x), "f"(v.y), "f"(v.z), "f"(v.w));
}

__global__ __launch_bounds__(256, 3)
void mesh_sampling_kernel(const float4* __restrict__ x,
                          const int*    __restrict__ cols,
                          const float*  __restrict__ vals,
                          float4*       __restrict__ out)
{
    const int gwarp = (blockIdx.x * blockDim.x + threadIdx.x) >> 5;
    const int lane  = threadIdx.x & 31;
    if (gwarp >= BP * MI) return;

    const int bp = gwarp / MI;           // batch pair 0..3
    const int mi = gwarp - bp * MI;
    const int m0 = mi * 2;
    const int m1 = m0 + 1;
    const int b0 = bp * 2;
    const int b1 = b0 + 1;

    // warp-uniform indices / weights (broadcast, L2-resident)
    const int  c00 = __ldg(cols + m0 * 3 + 0);
    const int  c01 = __ldg(cols + m0 * 3 + 1);
    const int  c02 = __ldg(cols + m0 * 3 + 2);
    const int  c10 = __ldg(cols + m1 * 3 + 0);
    const int  c11 = __ldg(cols + m1 * 3 + 1);
    const int  c12 = __ldg(cols + m1 * 3 + 2);
    const float v00 = __ldg(vals + m0 * 3 + 0);
    const float v01 = __ldg(vals + m0 * 3 + 1);
    const float v02 = __ldg(vals + m0 * 3 + 2);
    const float v10 = __ldg(vals + m1 * 3 + 0);
    const float v11 = __ldg(vals + m1 * 3 + 1);
    const float v12 = __ldg(vals + m1 * 3 + 2);

    const float4* xb0 = x + (size_t)b0 * N_DIM * C_VEC + lane;
    const float4* xb1 = x + (size_t)b1 * N_DIM * C_VEC + lane;

    // 12 independent 16B loads in flight, all 512B-row coalesced
    const float4 a00 = __ldg(xb0 + (size_t)c00 * C_VEC);
    const float4 a01 = __ldg(xb0 + (size_t)c01 * C_VEC);
    const float4 a02 = __ldg(xb0 + (size_t)c02 * C_VEC);
    const float4 a10 = __ldg(xb0 + (size_t)c10 * C_VEC);
    const float4 a11 = __ldg(xb0 + (size_t)c11 * C_VEC);
    const float4 a12 = __ldg(xb0 + (size_t)c12 * C_VEC);
    const float4 a20 = __ldg(xb1 + (size_t)c00 * C_VEC);
    const float4 a21 = __ldg(xb1 + (size_t)c01 * C_VEC);
    const float4 a22 = __ldg(xb1 + (size_t)c02 * C_VEC);
    const float4 a30 = __ldg(xb1 + (size_t)c10 * C_VEC);
    const float4 a31 = __ldg(xb1 + (size_t)c11 * C_VEC);
    const float4 a32 = __ldg(xb1 + (size_t)c12 * C_VEC);

    float4 r;
    // (b0, m0)
    r.x = v00 * a00.x + v01 * a01.x + v02 * a02.x;
    r.y = v00 * a00.y + v01 * a01.y + v02 * a02.y;
    r.z = v00 * a00.z + v01 * a01.z + v02 * a02.z;
    r.w = v00 * a00.w + v01 * a01.w + v02 * a02.w;
    stwt(out + ((size_t)b0 * M_DIM + m0) * C_VEC + lane, r);
    // (b0, m1)
    r.x = v10 * a10.x + v11 * a11.x + v12 * a12.x;
    r.y = v10 * a10.y + v11 * a11.y + v12 * a12.y;
    r.z = v10 * a10.z + v11 * a11.z + v12 * a12.z;
    r.w = v10 * a10.w + v11 * a11.w + v12 * a12.w;
    stwt(out + ((size_t)b0 * M_DIM + m1) * C_VEC + lane, r);
    // (b1, m0)
    r.x = v00 * a20.x + v01 * a21.x + v02 * a22.x;
    r.y = v00 * a20.y + v01 * a21.y + v02 * a22.y;
    r.z = v00 * a20.z + v01 * a21.z + v02 * a22.z;
    r.w = v00 * a20.w + v01 * a21.w + v02 * a22.w;
    stwt(out + ((size_t)b1 * M_DIM + m0) * C_VEC + lane, r);
    // (b1, m1)
    r.x = v10 * a30.x + v11 * a31.x + v12 * a32.x;
    r.y = v10 * a30.y + v11 * a31.y + v12 * a32.y;
    r.z = v10 * a30.z + v11 * a31.z + v12 * a32.z;
    r.w = v10 * a30.w + v11 * a31.w + v12 * a32.w;
    stwt(out + ((size_t)b1 * M_DIM + m1) * C_VEC + lane, r);
}

extern "C" void kernel_launch(void* const* d_in, const int* in_sizes, int n_in,
                              void* d_out, int out_size)
{
    const float4* x    = (const float4*)d_in[0];
    const int*    cols = (const int*)d_in[1];
    const float*  vals = (const float*)d_in[2];
    float4*       out  = (float4*)d_out;

    const int total_warps   = BP * MI;                // 50000
    const int threads       = 256;
    const int warps_per_blk = threads / 32;
    const int blocks        = (total_warps + warps_per_blk - 1) / warps_per_blk;

    mesh_sampling_kernel<<<blocks, threads>>>(x, cols, vals, out);
}

// round 13
// speedup vs baseline: 1.0456x; 1.0287x over previous
#include <cuda_runtime.h>
#include <cuda_bf16.h>
#include <cstdint>

// out[b,m,c] = sum_{k<3} vals[m,k] * x[b, cols[m,k], c]
//   x: [8, 50000, 128] f32   cols: [25000, 3] i32   vals: [25000, 3] f32
//   out: [8, 25000, 128] f32
//
// FINAL CONVERGED KERNEL (best of 11 measured rounds):
//  - DRAM-bound: ~230MB moved at ~5.8TB/s (the achievable ceiling for this
//    random-512B-gather + linear-write mix; invariant across MLP 3/6/12,
//    96KB/SM cp.async pipelining, L2 evict policies, occupancy, and
//    work-order remaps).
//  - Reads are BELOW the 159MB unique-row floor: L2 captures all within-
//    replay duplicate-row reuse (2 batch slices hot = 40MB << 126MB L2)
//    plus ~31MB cross-replay retention. Writes (102MB) are compulsory.
//  - one warp = 2 m-values x 2 batches: 12 independent coalesced LDG.128
//    per lane; every gather row = 4x128B lines, output = one 512B row.
//  - st.global.wt output: write-through keeps the write-once stream from
//    cycling dirty lines through L2 (the one measurably winning knob).
//  - monotone batch-pair order maximizes within-replay reuse capture.

#define B_DIM 8
#define N_DIM 50000
#define M_DIM 25000
#define C_VEC 32              // 128 floats / 4 per float4
#define BP    (B_DIM / 2)     // 4 batch pairs
#define MI    (M_DIM / 2)     // 12500 m pairs

__device__ __forceinline__ void stwt(float4* p, float4 v) {
    asm volatile("st.global.wt.v4.f32 [%0], {%1,%2,%3,%4};"
                 :: "l"(p), "f"(v.x), "f"(v.y), "f"(v.z), "f"(v.w));
}

__global__ __launch_bounds__(256, 3)
void mesh_sampling_kernel(const float4* __restrict__ x,
                          const int*    __restrict__ cols,
                          const float*  __restrict__ vals,
                          float4*       __restrict__ out)
{
    const int gwarp = (blockIdx.x * blockDim.x + threadIdx.x) >> 5;
    const int lane  = threadIdx.x & 31;
    if (gwarp >= BP * MI) return;

    const int bp = gwarp / MI;           // batch pair 0..3
    const int mi = gwarp - bp * MI;
    const int m0 = mi * 2;
    const int m1 = m0 + 1;
    const int b0 = bp * 2;
    const int b1 = b0 + 1;

    // warp-uniform indices / weights (broadcast, L2-resident)
    const int  c00 = __ldg(cols + m0 * 3 + 0);
    const int  c01 = __ldg(cols + m0 * 3 + 1);
    const int  c02 = __ldg(cols + m0 * 3 + 2);
    const int  c10 = __ldg(cols + m1 * 3 + 0);
    const int  c11 = __ldg(cols + m1 * 3 + 1);
    const int  c12 = __ldg(cols + m1 * 3 + 2);
    const float v00 = __ldg(vals + m0 * 3 + 0);
    const float v01 = __ldg(vals + m0 * 3 + 1);
    const float v02 = __ldg(vals + m0 * 3 + 2);
    const float v10 = __ldg(vals + m1 * 3 + 0);
    const float v11 = __ldg(vals + m1 * 3 + 1);
    const float v12 = __ldg(vals + m1 * 3 + 2);

    const float4* xb0 = x + (size_t)b0 * N_DIM * C_VEC + lane;
    const float4* xb1 = x + (size_t)b1 * N_DIM * C_VEC + lane;

    // 12 independent 16B loads in flight, all 512B-row coalesced
    const float4 a00 = __ldg(xb0 + (size_t)c00 * C_VEC);
    const float4 a01 = __ldg(xb0 + (size_t)c01 * C_VEC);
    const float4 a02 = __ldg(xb0 + (size_t)c02 * C_VEC);
    const float4 a10 = __ldg(xb0 + (size_t)c10 * C_VEC);
    const float4 a11 = __ldg(xb0 + (size_t)c11 * C_VEC);
    const float4 a12 = __ldg(xb0 + (size_t)c12 * C_VEC);
    const float4 a20 = __ldg(xb1 + (size_t)c00 * C_VEC);
    const float4 a21 = __ldg(xb1 + (size_t)c01 * C_VEC);
    const float4 a22 = __ldg(xb1 + (size_t)c02 * C_VEC);
    const float4 a30 = __ldg(xb1 + (size_t)c10 * C_VEC);
    const float4 a31 = __ldg(xb1 + (size_t)c11 * C_VEC);
    const float4 a32 = __ldg(xb1 + (size_t)c12 * C_VEC);

    float4 r;
    // (b0, m0)
    r.x = v00 * a00.x + v01 * a01.x + v02 * a02.x;
    r.y = v00 * a00.y + v01 * a01.y + v02 * a02.y;
    r.z = v00 * a00.z + v01 * a01.z + v02 * a02.z;
    r.w = v00 * a00.w + v01 * a01.w + v02 * a02.w;
    stwt(out + ((size_t)b0 * M_DIM + m0) * C_VEC + lane, r);
    // (b0, m1)
    r.x = v10 * a10.x + v11 * a11.x + v12 * a12.x;
    r.y = v10 * a10.y + v11 * a11.y + v12 * a12.y;
    r.z = v10 * a10.z + v11 * a11.z + v12 * a12.z;
    r.w = v10 * a10.w + v11 * a11.w + v12 * a12.w;
    stwt(out + ((size_t)b0 * M_DIM + m1) * C_VEC + lane, r);
    // (b1, m0)
    r.x = v00 * a20.x + v01 * a21.x + v02 * a22.x;
    r.y = v00 * a20.y + v01 * a21.y + v02 * a22.y;
    r.z = v00 * a20.z + v01 * a21.z + v02 * a22.z;
    r.w = v00 * a20.w + v01 * a21.w + v02 * a22.w;
    stwt(out + ((size_t)b1 * M_DIM + m0) * C_VEC + lane, r);
    // (b1, m1)
    r.x = v10 * a30.x + v11 * a31.x + v12 * a32.x;
    r.y = v10 * a30.y + v11 * a31.y + v12 * a32.y;
    r.z = v10 * a30.z + v11 * a31.z + v12 * a32.z;
    r.w = v10 * a30.w + v11 * a31.w + v12 * a32.w;
    stwt(out + ((size_t)b1 * M_DIM + m1) * C_VEC + lane, r);
}

extern "C" void kernel_launch(void* const* d_in, const int* in_sizes, int n_in,
                              void* d_out, int out_size)
{
    const float4* x    = (const float4*)d_in[0];
    const int*    cols = (const int*)d_in[1];
    const float*  vals = (const float*)d_in[2];
    float4*       out  = (float4*)d_out;

    const int total_warps   = BP * MI;                // 50000
    const int threads       = 256;
    const int warps_per_blk = threads / 32;
    const int blocks        = (total_warps + warps_per_blk - 1) / warps_per_blk;

    mesh_sampling_kernel<<<blocks, threads>>>(x, cols, vals, out);
}